// round 3
// baseline (speedup 1.0000x reference)
#include <cuda_runtime.h>

// ---------------- problem constants ----------------
#define Bb    4
#define Nn    4096
#define Eraw  131072
#define Etot  (Eraw + Nn)        // 135168 (self loops appended)
#define Fin   768
#define HIDD  64
#define NHEAD 4
#define HD    256                // NHEAD * HIDD
#define NCLS  6

// ---------------- scratch (device globals; no allocation allowed) ----------------
__device__ float g_h  [Bb * Nn * HD];
__device__ float g_o  [Bb * Nn * HD];
__device__ float g_as [Bb * Nn * NHEAD];
__device__ float g_ad [Bb * Nn * NHEAD];
__device__ float g_m  [Bb * Nn * NHEAD];
__device__ float g_den[Bb * Nn * NHEAD];
__device__ float g_ex [Bb * Etot * NHEAD];
__device__ int   g_cnt[Bb * Nn];
__device__ int   g_rp [Bb * (Nn + 1)];
__device__ int   g_cur[Bb * Nn];
__device__ int   g_csrc[Bb * Etot];
__device__ int   g_cdst[Bb * Etot];
__device__ float g_emb[Bb * HIDD];

// ---------------- helpers ----------------
typedef unsigned long long u64t;

__device__ __forceinline__ u64t pack2(float lo, float hi) {
    u64t r;
    asm("mov.b64 %0, {%1, %2};" : "=l"(r) : "r"(__float_as_uint(lo)), "r"(__float_as_uint(hi)));
    return r;
}
__device__ __forceinline__ u64t fma2(u64t a, u64t b, u64t c) {
    u64t d;
    asm("fma.rn.f32x2 %0, %1, %2, %3;" : "=l"(d) : "l"(a), "l"(b), "l"(c));
    return d;
}
__device__ __forceinline__ float2 unpack2(u64t v) {
    unsigned lo, hi;
    asm("mov.b64 {%0, %1}, %2;" : "=r"(lo), "=r"(hi) : "l"(v));
    float2 f; f.x = __uint_as_float(lo); f.y = __uint_as_float(hi);
    return f;
}

__device__ __forceinline__ void atomicMaxF(float* addr, float v) {
    if (v >= 0.f) atomicMax((int*)addr, __float_as_int(v));
    else          atomicMin((unsigned int*)addr, __float_as_uint(v));
}

// ---------------- CSR build ----------------
__global__ void k_zerocnt() {
    int i = blockIdx.x * blockDim.x + threadIdx.x;
    if (i < Bb * Nn) g_cnt[i] = 0;
}

__global__ void k_hist(const int* __restrict__ ei) {
    int i = blockIdx.x * blockDim.x + threadIdx.x;
    if (i >= Bb * Etot) return;
    int g = i / Etot, e = i - g * Etot;
    int dst = (e < Eraw) ? ei[(g * 2 + 1) * Eraw + e] : (e - Eraw);
    atomicAdd(&g_cnt[g * Nn + dst], 1);
}

__global__ void k_scan() {   // one block per graph, 1024 threads, 4 elems/thread
    int g = blockIdx.x;
    __shared__ int sh[1024];
    int t = threadIdx.x;
    const int* cnt = g_cnt + g * Nn;
    int b4 = t * 4;
    int v0 = cnt[b4], v1 = cnt[b4 + 1], v2 = cnt[b4 + 2], v3 = cnt[b4 + 3];
    int s1 = v0, s2 = s1 + v1, s3 = s2 + v2, s4 = s3 + v3;
    sh[t] = s4;
    __syncthreads();
    for (int off = 1; off < 1024; off <<= 1) {
        int x = (t >= off) ? sh[t - off] : 0;
        __syncthreads();
        sh[t] += x;
        __syncthreads();
    }
    int base = sh[t] - s4;
    int* rp  = g_rp  + g * (Nn + 1);
    int* cur = g_cur + g * Nn;
    if (t == 0) rp[0] = 0;
    rp[b4 + 1] = base + s1; rp[b4 + 2] = base + s2;
    rp[b4 + 3] = base + s3; rp[b4 + 4] = base + s4;
    cur[b4] = base; cur[b4 + 1] = base + s1; cur[b4 + 2] = base + s2; cur[b4 + 3] = base + s3;
}

__global__ void k_scatter(const int* __restrict__ ei) {
    int i = blockIdx.x * blockDim.x + threadIdx.x;
    if (i >= Bb * Etot) return;
    int g = i / Etot, e = i - g * Etot;
    int src, dst;
    if (e < Eraw) { src = ei[(g * 2) * Eraw + e]; dst = ei[(g * 2 + 1) * Eraw + e]; }
    else          { src = e - Eraw; dst = src; }
    int pos = atomicAdd(&g_cur[g * Nn + dst], 1);
    int slot = g * Etot + pos;
    g_csrc[slot] = src;
    g_cdst[slot] = dst;
}

// ---------------- SGEMM (64x64x16 tile, 4x4 micro, packed f32x2 FMA) ----------------
__global__ __launch_bounds__(256)
void sgemm(const float* __restrict__ A, const float* __restrict__ B,
           float* __restrict__ C, int M, int N, int K) {
    __shared__ float As[16][68];
    __shared__ float Bs[16][64];
    const int tid = threadIdx.x;
    const int tx = tid & 15, ty = tid >> 4;
    const int row0 = blockIdx.y * 64, col0 = blockIdx.x * 64;

    const int ar = tid >> 2, ak = (tid & 3) * 4;
    const int bk = tid >> 4, bn = (tid & 15) * 4;

    u64t acc[4][2];
#pragma unroll
    for (int i = 0; i < 4; i++) { acc[i][0] = 0ull; acc[i][1] = 0ull; }

    for (int k0 = 0; k0 < K; k0 += 16) {
        float4 av4 = *(const float4*)&A[(row0 + ar) * K + k0 + ak];
        As[ak + 0][ar] = av4.x; As[ak + 1][ar] = av4.y;
        As[ak + 2][ar] = av4.z; As[ak + 3][ar] = av4.w;
        *(float4*)&Bs[bk][bn] = *(const float4*)&B[(k0 + bk) * N + col0 + bn];
        __syncthreads();
#pragma unroll
        for (int k = 0; k < 16; k++) {
            float4 a4 = *(const float4*)&As[k][ty * 4];
            float4 b4 = *(const float4*)&Bs[k][tx * 4];
            u64t b01 = pack2(b4.x, b4.y), b23 = pack2(b4.z, b4.w);
            float av[4] = {a4.x, a4.y, a4.z, a4.w};
#pragma unroll
            for (int i = 0; i < 4; i++) {
                u64t ai = pack2(av[i], av[i]);
                acc[i][0] = fma2(ai, b01, acc[i][0]);
                acc[i][1] = fma2(ai, b23, acc[i][1]);
            }
        }
        __syncthreads();
    }
#pragma unroll
    for (int i = 0; i < 4; i++) {
        float2 p0 = unpack2(acc[i][0]), p1 = unpack2(acc[i][1]);
        float4 v; v.x = p0.x; v.y = p0.y; v.z = p1.x; v.w = p1.y;
        *(float4*)&C[(row0 + ty * 4 + i) * N + col0 + tx * 4] = v;
    }
}

// ---------------- attention coefficients + softmax state init ----------------
template <int H>
__global__ void k_coef(const float* __restrict__ att_s, const float* __restrict__ att_d) {
    int w = (blockIdx.x * blockDim.x + threadIdx.x) >> 5;
    int lane = threadIdx.x & 31;
    if (w >= Bb * Nn * H) return;
    int nn = w / H, h = w - nn * H;
    const float* hp = g_h + nn * (H * 64) + h * 64;
    float v0 = hp[lane], v1 = hp[lane + 32];
    float s = v0 * att_s[h * 64 + lane] + v1 * att_s[h * 64 + lane + 32];
    float d = v0 * att_d[h * 64 + lane] + v1 * att_d[h * 64 + lane + 32];
#pragma unroll
    for (int o = 16; o; o >>= 1) {
        s += __shfl_xor_sync(0xffffffffu, s, o);
        d += __shfl_xor_sync(0xffffffffu, d, o);
    }
    if (lane == 0) {
        g_as[w] = s; g_ad[w] = d;
        g_m[w] = __int_as_float(0xFF800000);   // -inf
        g_den[w] = 0.f;
    }
}

// ---------------- edge pass 1: leaky-relu logits + segment max ----------------
template <int H>
__global__ void k_edgeA() {
    int i = blockIdx.x * blockDim.x + threadIdx.x;
    if (i >= Bb * Etot) return;
    int g = i / Etot;
    int src = g_csrc[i], dst = g_cdst[i];
    int bs = (g * Nn + src) * H, bd = (g * Nn + dst) * H;
#pragma unroll
    for (int h = 0; h < H; h++) {
        float e = g_as[bs + h] + g_ad[bd + h];
        e = (e > 0.f) ? e : 0.2f * e;
        g_ex[(long long)i * H + h] = e;
        atomicMaxF(&g_m[bd + h], e);
    }
}

// ---------------- edge pass 2: exp + segment sum ----------------
template <int H>
__global__ void k_edgeB() {
    int i = blockIdx.x * blockDim.x + threadIdx.x;
    if (i >= Bb * Etot) return;
    int g = i / Etot;
    int dst = g_cdst[i];
    int bd = (g * Nn + dst) * H;
#pragma unroll
    for (int h = 0; h < H; h++) {
        float e = g_ex[(long long)i * H + h];
        float ex = __expf(e - g_m[bd + h]);
        g_ex[(long long)i * H + h] = ex;
        atomicAdd(&g_den[bd + h], ex);
    }
}

// ---------------- aggregation: warp per destination node, atomic-free ----------------
template <int H, bool DOELU>
__global__ void k_agg(const float* __restrict__ bias, float* __restrict__ out) {
    constexpr int CH = H * 64;
    constexpr int PER = CH / 32;
    int w = (blockIdx.x * blockDim.x + threadIdx.x) >> 5;
    int lane = threadIdx.x & 31;
    if (w >= Bb * Nn) return;
    int g = w / Nn, n = w - g * Nn;
    int s = g_rp[g * (Nn + 1) + n], e = g_rp[g * (Nn + 1) + n + 1];
    int head = (lane * PER) >> 6;

    float acc[PER];
#pragma unroll
    for (int k = 0; k < PER; k++) acc[k] = 0.f;

    for (int i = s; i < e; i++) {
        int slot = g * Etot + i;
        int src = g_csrc[slot];
        float alpha = g_ex[(long long)slot * H + head];
        const float* hp = g_h + (g * Nn + src) * CH + lane * PER;
        if (PER == 8) {
            float4 x0 = *(const float4*)hp;
            float4 x1 = *(const float4*)(hp + 4);
            acc[0] += alpha * x0.x; acc[1] += alpha * x0.y;
            acc[2] += alpha * x0.z; acc[3] += alpha * x0.w;
            acc[4] += alpha * x1.x; acc[5] += alpha * x1.y;
            acc[6] += alpha * x1.z; acc[7] += alpha * x1.w;
        } else {
            float2 x0 = *(const float2*)hp;
            acc[0] += alpha * x0.x; acc[1] += alpha * x0.y;
        }
    }
    float inv = 1.f / (g_den[(g * Nn + n) * H + head] + 1e-16f);
    float* op = out + (long long)w * CH + lane * PER;
#pragma unroll
    for (int k = 0; k < PER; k++) {
        float v = acc[k] * inv + bias[lane * PER + k];
        if (DOELU) v = (v > 0.f) ? v : expm1f(v);
        op[k] = v;
    }
}

// ---------------- graph embed: mean over nodes ----------------
__global__ void k_mean() {
    int c = blockIdx.x, g = blockIdx.y;
    __shared__ float sh[256];
    float s = 0.f;
    for (int n = threadIdx.x; n < Nn; n += 256)
        s += g_o[(long long)(g * Nn + n) * HIDD + c];
    sh[threadIdx.x] = s;
    __syncthreads();
    for (int o = 128; o; o >>= 1) {
        if (threadIdx.x < o) sh[threadIdx.x] += sh[threadIdx.x + o];
        __syncthreads();
    }
    if (threadIdx.x == 0) g_emb[g * HIDD + c] = sh[0] * (1.f / Nn);
}

// ---------------- classifier + log-softmax + loss/pred ----------------
__global__ void k_final(const int* __restrict__ labels, const float* __restrict__ Wc,
                        const float* __restrict__ bc, float* __restrict__ out, int out_size) {
    __shared__ float lg[Bb][NCLS];
    __shared__ float nll[Bb];
    __shared__ float predf[Bb];
    int t = threadIdx.x;
    if (t < Bb * NCLS) {
        int g = t / NCLS, c = t - g * NCLS;
        float s = bc[c];
#pragma unroll 8
        for (int d = 0; d < HIDD; d++) s += g_emb[g * HIDD + d] * Wc[d * NCLS + c];
        lg[g][c] = s;
    }
    __syncthreads();
    if (t < Bb) {
        float mx = lg[t][0]; int am = 0;
#pragma unroll
        for (int c = 1; c < NCLS; c++) if (lg[t][c] > mx) { mx = lg[t][c]; am = c; }
        float se = 0.f;
#pragma unroll
        for (int c = 0; c < NCLS; c++) se += expf(lg[t][c] - mx);
        float lse = mx + logf(se);
        nll[t] = lse - lg[t][labels[t]];
        predf[t] = (float)am;
    }
    __syncthreads();
    if (t == 0) {
        float loss = (nll[0] + nll[1] + nll[2] + nll[3]) * 0.25f;
        if (out_size >= 9) {
            for (int g = 0; g < Bb; g++) { out[g] = predf[g]; out[4 + g] = (float)labels[g]; }
            out[8] = loss;
            for (int j = 9; j < out_size; j++) out[j] = 0.f;
        } else if (out_size == 1) {
            out[0] = loss;
        } else if (out_size == 4) {
            for (int g = 0; g < Bb; g++) out[g] = predf[g];
        } else if (out_size == 8) {
            for (int g = 0; g < Bb; g++) { out[g] = predf[g]; out[4 + g] = (float)labels[g]; }
        } else {
            for (int j = 0; j < out_size; j++) out[j] = loss;
        }
    }
}

// ---------------- host launcher ----------------
extern "C" void kernel_launch(void* const* d_in, const int* in_sizes, int n_in,
                              void* d_out, int out_size) {
    const float* x      = (const float*)d_in[0];
    const int*   labels = (const int*)  d_in[1];
    const int*   ei     = (const int*)  d_in[2];
    const float* W1  = (const float*)d_in[3];
    const float* as1 = (const float*)d_in[4];
    const float* ad1 = (const float*)d_in[5];
    const float* b1  = (const float*)d_in[6];
    const float* W2  = (const float*)d_in[7];
    const float* as2 = (const float*)d_in[8];
    const float* ad2 = (const float*)d_in[9];
    const float* b2  = (const float*)d_in[10];
    const float* W3  = (const float*)d_in[11];
    const float* as3 = (const float*)d_in[12];
    const float* ad3 = (const float*)d_in[13];
    const float* b3  = (const float*)d_in[14];
    const float* Wc  = (const float*)d_in[15];
    const float* bc  = (const float*)d_in[16];
    float* out = (float*)d_out;

    float *p_h, *p_o;
    cudaGetSymbolAddress((void**)&p_h, g_h);
    cudaGetSymbolAddress((void**)&p_o, g_o);

    const int M = Bb * Nn;
    const int EBLK = (Bb * Etot + 255) / 256;

    // CSR build (shared across all layers)
    k_zerocnt<<<(Bb * Nn + 255) / 256, 256>>>();
    k_hist<<<EBLK, 256>>>(ei);
    k_scan<<<Bb, 1024>>>();
    k_scatter<<<EBLK, 256>>>(ei);

    // layer 1
    sgemm<<<dim3(HD / 64, M / 64), 256>>>(x, W1, p_h, M, HD, Fin);
    k_coef<NHEAD><<<(M * NHEAD) / 8, 256>>>(as1, ad1);
    k_edgeA<NHEAD><<<EBLK, 256>>>();
    k_edgeB<NHEAD><<<EBLK, 256>>>();
    k_agg<NHEAD, true><<<M / 8, 256>>>(b1, p_o);

    // layer 2
    sgemm<<<dim3(HD / 64, M / 64), 256>>>(p_o, W2, p_h, M, HD, HD);
    k_coef<NHEAD><<<(M * NHEAD) / 8, 256>>>(as2, ad2);
    k_edgeA<NHEAD><<<EBLK, 256>>>();
    k_edgeB<NHEAD><<<EBLK, 256>>>();
    k_agg<NHEAD, true><<<M / 8, 256>>>(b2, p_o);

    // layer 3
    sgemm<<<dim3(HIDD / 64, M / 64), 256>>>(p_o, W3, p_h, M, HIDD, HD);
    k_coef<1><<<M / 8, 256>>>(as3, ad3);
    k_edgeA<1><<<EBLK, 256>>>();
    k_edgeB<1><<<EBLK, 256>>>();
    k_agg<1, false><<<M / 8, 256>>>(b3, p_o);

    // readout + classifier
    k_mean<<<dim3(HIDD, Bb), 256>>>();
    k_final<<<1, 32>>>(labels, Wc, bc, out, out_size);
}

// round 4
// speedup vs baseline: 1.2608x; 1.2608x over previous
#include <cuda_runtime.h>

// ---------------- problem constants ----------------
#define Bb    4
#define Nn    4096
#define Eraw  131072
#define Etot  (Eraw + Nn)        // 135168 (self loops appended)
#define Fin   768
#define HIDD  64
#define NHEAD 4
#define HD    256                // NHEAD * HIDD
#define NCLS  6
#define DEGCAP 96                // smem alpha cache per node (deg tail ~Poisson(33))

// ---------------- scratch (device globals; no allocation allowed) ----------------
__device__ float g_h  [Bb * Nn * HD];        // GEMM output (pre-aggregation)
__device__ float g_o  [Bb * Nn * HD];        // layer output
__device__ float g_as [Bb * Nn * NHEAD];
__device__ float g_ad [Bb * Nn * NHEAD];
__device__ int   g_cnt[Bb * Nn];
__device__ int   g_rp [Bb * (Nn + 1)];
__device__ int   g_cur[Bb * Nn];
__device__ int   g_csrc[Bb * Etot];
__device__ float g_emb[Bb * HIDD];

// ---------------- helpers ----------------
typedef unsigned long long u64t;

__device__ __forceinline__ u64t pack2(float lo, float hi) {
    u64t r;
    asm("mov.b64 %0, {%1, %2};" : "=l"(r) : "r"(__float_as_uint(lo)), "r"(__float_as_uint(hi)));
    return r;
}
__device__ __forceinline__ u64t fma2(u64t a, u64t b, u64t c) {
    u64t d;
    asm("fma.rn.f32x2 %0, %1, %2, %3;" : "=l"(d) : "l"(a), "l"(b), "l"(c));
    return d;
}
__device__ __forceinline__ float2 unpack2(u64t v) {
    unsigned lo, hi;
    asm("mov.b64 {%0, %1}, %2;" : "=r"(lo), "=r"(hi) : "l"(v));
    float2 f; f.x = __uint_as_float(lo); f.y = __uint_as_float(hi);
    return f;
}

// ---------------- CSR build ----------------
__global__ void k_zerocnt() {
    int i = blockIdx.x * blockDim.x + threadIdx.x;
    if (i < Bb * Nn) g_cnt[i] = 0;
}

__global__ void k_hist(const int* __restrict__ ei) {
    int i = blockIdx.x * blockDim.x + threadIdx.x;
    if (i >= Bb * Etot) return;
    int g = i / Etot, e = i - g * Etot;
    int dst = (e < Eraw) ? ei[(g * 2 + 1) * Eraw + e] : (e - Eraw);
    atomicAdd(&g_cnt[g * Nn + dst], 1);
}

__global__ void k_scan() {   // one block per graph, 1024 threads, 4 elems/thread
    int g = blockIdx.x;
    __shared__ int sh[1024];
    int t = threadIdx.x;
    const int* cnt = g_cnt + g * Nn;
    int b4 = t * 4;
    int v0 = cnt[b4], v1 = cnt[b4 + 1], v2 = cnt[b4 + 2], v3 = cnt[b4 + 3];
    int s1 = v0, s2 = s1 + v1, s3 = s2 + v2, s4 = s3 + v3;
    sh[t] = s4;
    __syncthreads();
    for (int off = 1; off < 1024; off <<= 1) {
        int x = (t >= off) ? sh[t - off] : 0;
        __syncthreads();
        sh[t] += x;
        __syncthreads();
    }
    int base = sh[t] - s4;
    int* rp  = g_rp  + g * (Nn + 1);
    int* cur = g_cur + g * Nn;
    if (t == 0) rp[0] = 0;
    rp[b4 + 1] = base + s1; rp[b4 + 2] = base + s2;
    rp[b4 + 3] = base + s3; rp[b4 + 4] = base + s4;
    cur[b4] = base; cur[b4 + 1] = base + s1; cur[b4 + 2] = base + s2; cur[b4 + 3] = base + s3;
}

__global__ void k_scatter(const int* __restrict__ ei) {
    int i = blockIdx.x * blockDim.x + threadIdx.x;
    if (i >= Bb * Etot) return;
    int g = i / Etot, e = i - g * Etot;
    int src, dst;
    if (e < Eraw) { src = ei[(g * 2) * Eraw + e]; dst = ei[(g * 2 + 1) * Eraw + e]; }
    else          { src = e - Eraw; dst = src; }
    int pos = atomicAdd(&g_cur[g * Nn + dst], 1);
    g_csrc[g * Etot + pos] = src;
}

// ---------------- SGEMM 64x64x16 + fused attention-coefficient epilogue ----------------
// Each 64-wide column tile of the output is exactly one head (head dim = 64),
// so a_s/a_d for that head are computed right here from the accumulators.
__global__ __launch_bounds__(256)
void sgemm(const float* __restrict__ A, const float* __restrict__ B,
           float* __restrict__ C, int M, int N, int K,
           const float* __restrict__ att_s, const float* __restrict__ att_d, int H) {
    __shared__ float As[16][68];
    __shared__ float Bs[16][64];
    const int tid = threadIdx.x;
    const int tx = tid & 15, ty = tid >> 4;
    const int row0 = blockIdx.y * 64, col0 = blockIdx.x * 64;

    const int ar = tid >> 2, ak = (tid & 3) * 4;
    const int bk = tid >> 4, bn = (tid & 15) * 4;

    u64t acc[4][2];
#pragma unroll
    for (int i = 0; i < 4; i++) { acc[i][0] = 0ull; acc[i][1] = 0ull; }

    for (int k0 = 0; k0 < K; k0 += 16) {
        float4 av4 = *(const float4*)&A[(row0 + ar) * K + k0 + ak];
        As[ak + 0][ar] = av4.x; As[ak + 1][ar] = av4.y;
        As[ak + 2][ar] = av4.z; As[ak + 3][ar] = av4.w;
        *(float4*)&Bs[bk][bn] = *(const float4*)&B[(k0 + bk) * N + col0 + bn];
        __syncthreads();
#pragma unroll
        for (int k = 0; k < 16; k++) {
            float4 a4 = *(const float4*)&As[k][ty * 4];
            float4 b4 = *(const float4*)&Bs[k][tx * 4];
            u64t b01 = pack2(b4.x, b4.y), b23 = pack2(b4.z, b4.w);
            float av[4] = {a4.x, a4.y, a4.z, a4.w};
#pragma unroll
            for (int i = 0; i < 4; i++) {
                u64t ai = pack2(av[i], av[i]);
                acc[i][0] = fma2(ai, b01, acc[i][0]);
                acc[i][1] = fma2(ai, b23, acc[i][1]);
            }
        }
        __syncthreads();
    }

    // unpack, store C, and compute per-row head dots
    const int head = col0 >> 6;
    float ws[4], wd[4];
#pragma unroll
    for (int j = 0; j < 4; j++) {
        ws[j] = att_s[head * 64 + tx * 4 + j];
        wd[j] = att_d[head * 64 + tx * 4 + j];
    }
#pragma unroll
    for (int i = 0; i < 4; i++) {
        float2 p0 = unpack2(acc[i][0]), p1 = unpack2(acc[i][1]);
        float v0 = p0.x, v1 = p0.y, v2 = p1.x, v3 = p1.y;
        float4 v; v.x = v0; v.y = v1; v.z = v2; v.w = v3;
        *(float4*)&C[(row0 + ty * 4 + i) * N + col0 + tx * 4] = v;

        float ps = v0 * ws[0] + v1 * ws[1] + v2 * ws[2] + v3 * ws[3];
        float pd = v0 * wd[0] + v1 * wd[1] + v2 * wd[2] + v3 * wd[3];
#pragma unroll
        for (int off = 8; off; off >>= 1) {
            ps += __shfl_xor_sync(0xffffffffu, ps, off);
            pd += __shfl_xor_sync(0xffffffffu, pd, off);
        }
        if (tx == 0) {
            int row = row0 + ty * 4 + i;
            g_as[row * H + head] = ps;
            g_ad[row * H + head] = pd;
        }
    }
}

// ---------------- fused edge-softmax + aggregation: warp per destination ----------------
// Pass 1: lanes parallelize over edges, compute exp(leaky(as[src]+ad[dst])) per head,
//         warp-reduce denominator, cache alphas in smem (recompute fallback past DEGCAP).
// Pass 2: coalesced row gather of h[src], scaled by alpha, normalized, bias(+ELU).
template <int H, bool DOELU>
__global__ __launch_bounds__(256)
void attn_agg(const float* __restrict__ bias, float* __restrict__ out) {
    constexpr int CH  = H * 64;
    constexpr int PER = CH / 32;
    __shared__ float sh_alpha[8][DEGCAP * H];

    int w = (blockIdx.x * blockDim.x + threadIdx.x) >> 5;
    int wl = (threadIdx.x >> 5);
    int lane = threadIdx.x & 31;
    if (w >= Bb * Nn) return;
    int g = w / Nn, n = w - g * Nn;
    int s = g_rp[g * (Nn + 1) + n], e = g_rp[g * (Nn + 1) + n + 1];

    // broadcast ad[dst] per head
    float adv = 0.f;
    if (lane < H) adv = g_ad[(g * Nn + n) * H + lane];
    float ad_h[H];
#pragma unroll
    for (int h = 0; h < H; h++) ad_h[h] = __shfl_sync(0xffffffffu, adv, h);

    // pass 1: denominator + alpha cache
    float den[H];
#pragma unroll
    for (int h = 0; h < H; h++) den[h] = 0.f;

    for (int i = s + lane; i < e; i += 32) {
        int src = g_csrc[g * Etot + i];
        float av[H];
        if (H == 4) {
            float4 a4 = *(const float4*)&g_as[((long long)g * Nn + src) * 4];
            av[0] = a4.x; if (H > 1) { av[1] = a4.y; av[2] = a4.z; av[3] = a4.w; }
        } else {
            av[0] = g_as[(g * Nn + src)];
        }
        int rel = i - s;
#pragma unroll
        for (int h = 0; h < H; h++) {
            float eh = av[h] + ad_h[h];
            eh = (eh > 0.f) ? eh : 0.2f * eh;
            float ex = __expf(eh);
            den[h] += ex;
            if (rel < DEGCAP) sh_alpha[wl][rel * H + h] = ex;
        }
    }
#pragma unroll
    for (int h = 0; h < H; h++)
#pragma unroll
        for (int off = 16; off; off >>= 1)
            den[h] += __shfl_xor_sync(0xffffffffu, den[h], off);
    __syncwarp();

    const int head = (lane * PER) >> 6;
    const float invh = 1.f / (den[head] + 1e-16f);
    float adh = ad_h[head];

    // pass 2: weighted gather
    float acc[PER];
#pragma unroll
    for (int k = 0; k < PER; k++) acc[k] = 0.f;

    for (int i = s; i < e; i++) {
        int slot = g * Etot + i;
        int src = g_csrc[slot];
        int rel = i - s;
        float ex;
        if (rel < DEGCAP) {
            ex = sh_alpha[wl][rel * H + head];
        } else {
            float a = g_as[((long long)g * Nn + src) * H + head];
            float eh = a + adh;
            eh = (eh > 0.f) ? eh : 0.2f * eh;
            ex = __expf(eh);
        }
        const float* hp = g_h + ((long long)g * Nn + src) * CH + lane * PER;
        if (PER == 8) {
            float4 x0 = __ldg((const float4*)hp);
            float4 x1 = __ldg((const float4*)(hp + 4));
            acc[0] += ex * x0.x; acc[1] += ex * x0.y;
            acc[2] += ex * x0.z; acc[3] += ex * x0.w;
            acc[4] += ex * x1.x; acc[5] += ex * x1.y;
            acc[6] += ex * x1.z; acc[7] += ex * x1.w;
        } else {
            float2 x0 = __ldg((const float2*)hp);
            acc[0] += ex * x0.x; acc[1] += ex * x0.y;
        }
    }

    float* op = out + (long long)w * CH + lane * PER;
#pragma unroll
    for (int k = 0; k < PER; k++) {
        float v = acc[k] * invh + bias[lane * PER + k];
        if (DOELU) v = (v > 0.f) ? v : expm1f(v);
        op[k] = v;
    }
}

// ---------------- graph embed: mean over nodes ----------------
__global__ void k_mean() {
    int c = blockIdx.x, g = blockIdx.y;
    __shared__ float sh[256];
    float s = 0.f;
    for (int n = threadIdx.x; n < Nn; n += 256)
        s += g_o[(long long)(g * Nn + n) * HIDD + c];
    sh[threadIdx.x] = s;
    __syncthreads();
    for (int o = 128; o; o >>= 1) {
        if (threadIdx.x < o) sh[threadIdx.x] += sh[threadIdx.x + o];
        __syncthreads();
    }
    if (threadIdx.x == 0) g_emb[g * HIDD + c] = sh[0] * (1.f / Nn);
}

// ---------------- classifier + log-softmax + loss/pred ----------------
__global__ void k_final(const int* __restrict__ labels, const float* __restrict__ Wc,
                        const float* __restrict__ bc, float* __restrict__ out, int out_size) {
    __shared__ float lg[Bb][NCLS];
    __shared__ float nll[Bb];
    __shared__ float predf[Bb];
    int t = threadIdx.x;
    if (t < Bb * NCLS) {
        int g = t / NCLS, c = t - g * NCLS;
        float s = bc[c];
#pragma unroll 8
        for (int d = 0; d < HIDD; d++) s += g_emb[g * HIDD + d] * Wc[d * NCLS + c];
        lg[g][c] = s;
    }
    __syncthreads();
    if (t < Bb) {
        float mx = lg[t][0]; int am = 0;
#pragma unroll
        for (int c = 1; c < NCLS; c++) if (lg[t][c] > mx) { mx = lg[t][c]; am = c; }
        float se = 0.f;
#pragma unroll
        for (int c = 0; c < NCLS; c++) se += expf(lg[t][c] - mx);
        float lse = mx + logf(se);
        nll[t] = lse - lg[t][labels[t]];
        predf[t] = (float)am;
    }
    __syncthreads();
    if (t == 0) {
        float loss = (nll[0] + nll[1] + nll[2] + nll[3]) * 0.25f;
        if (out_size >= 9) {
            for (int g = 0; g < Bb; g++) { out[g] = predf[g]; out[4 + g] = (float)labels[g]; }
            out[8] = loss;
            for (int j = 9; j < out_size; j++) out[j] = 0.f;
        } else if (out_size == 1) {
            out[0] = loss;
        } else if (out_size == 4) {
            for (int g = 0; g < Bb; g++) out[g] = predf[g];
        } else if (out_size == 8) {
            for (int g = 0; g < Bb; g++) { out[g] = predf[g]; out[4 + g] = (float)labels[g]; }
        } else {
            for (int j = 0; j < out_size; j++) out[j] = loss;
        }
    }
}

// ---------------- host launcher ----------------
extern "C" void kernel_launch(void* const* d_in, const int* in_sizes, int n_in,
                              void* d_out, int out_size) {
    const float* x      = (const float*)d_in[0];
    const int*   labels = (const int*)  d_in[1];
    const int*   ei     = (const int*)  d_in[2];
    const float* W1  = (const float*)d_in[3];
    const float* as1 = (const float*)d_in[4];
    const float* ad1 = (const float*)d_in[5];
    const float* b1  = (const float*)d_in[6];
    const float* W2  = (const float*)d_in[7];
    const float* as2 = (const float*)d_in[8];
    const float* ad2 = (const float*)d_in[9];
    const float* b2  = (const float*)d_in[10];
    const float* W3  = (const float*)d_in[11];
    const float* as3 = (const float*)d_in[12];
    const float* ad3 = (const float*)d_in[13];
    const float* b3  = (const float*)d_in[14];
    const float* Wc  = (const float*)d_in[15];
    const float* bc  = (const float*)d_in[16];
    float* out = (float*)d_out;

    float *p_h, *p_o;
    cudaGetSymbolAddress((void**)&p_h, g_h);
    cudaGetSymbolAddress((void**)&p_o, g_o);

    const int M = Bb * Nn;
    const int EBLK = (Bb * Etot + 255) / 256;

    // CSR build (shared across all layers)
    k_zerocnt<<<(Bb * Nn + 255) / 256, 256>>>();
    k_hist<<<EBLK, 256>>>(ei);
    k_scan<<<Bb, 1024>>>();
    k_scatter<<<EBLK, 256>>>(ei);

    // layer 1: 768 -> 4x64, concat, elu
    sgemm<<<dim3(HD / 64, M / 64), 256>>>(x, W1, p_h, M, HD, Fin, as1, ad1, NHEAD);
    attn_agg<NHEAD, true><<<M / 8, 256>>>(b1, p_o);

    // layer 2: 256 -> 4x64, concat, elu
    sgemm<<<dim3(HD / 64, M / 64), 256>>>(p_o, W2, p_h, M, HD, HD, as2, ad2, NHEAD);
    attn_agg<NHEAD, true><<<M / 8, 256>>>(b2, p_o);

    // layer 3: 256 -> 1x64, mean(=identity over 1 head), no elu
    sgemm<<<dim3(HIDD / 64, M / 64), 256>>>(p_o, W3, p_h, M, HIDD, HD, as3, ad3, 1);
    attn_agg<1, false><<<M / 8, 256>>>(b3, p_o);

    // readout + classifier
    k_mean<<<dim3(HIDD, Bb), 256>>>();
    k_final<<<1, 32>>>(labels, Wc, bc, out, out_size);
}

// round 6
// speedup vs baseline: 1.7518x; 1.3894x over previous
#include <cuda_runtime.h>
#include <cuda_bf16.h>
#include <cstdint>

// ---------------- problem constants ----------------
#define Bb    4
#define Nn    4096
#define Eraw  131072
#define Etot  (Eraw + Nn)        // 135168 (self loops appended)
#define Fin   768
#define HIDD  64
#define NHEAD 4
#define HD    256                // NHEAD * HIDD
#define NCLS  6
#define DEGCAP 96
#define Mtot  (Bb * Nn)          // 16384

// weight-transpose segment sizes (row-major [N x K] transposed copies)
#define WT1   (HD * Fin)         // 196608
#define WT2   (HD * HD)          // 65536
#define WT3   (HIDD * HD)        // 16384
#define WTALL (WT1 + WT2 + WT3)

// ---------------- scratch (device globals; no allocation allowed) ----------------
__device__ float g_h  [Mtot * HD];           // GEMM output (fp32, for aggregation gather)
__device__ float g_o  [Mtot * HIDD];         // layer-3 output (fp32, for k_mean)
__device__ __nv_bfloat16 g_oh[Mtot * HD];    // layer output hi (feeds next GEMM A)
__device__ __nv_bfloat16 g_ol[Mtot * HD];    // layer output lo
__device__ __nv_bfloat16 g_xh[Mtot * Fin];   // x hi
__device__ __nv_bfloat16 g_xl[Mtot * Fin];   // x lo
__device__ __nv_bfloat16 g_wth[WTALL];       // transposed weights hi
__device__ __nv_bfloat16 g_wtl[WTALL];       // transposed weights lo
__device__ float g_as [Mtot * NHEAD];
__device__ float g_ad [Mtot * NHEAD];
__device__ int   g_cnt[Bb * Nn];
__device__ int   g_rp [Bb * (Nn + 1)];
__device__ int   g_cur[Bb * Nn];
__device__ int   g_csrc[Bb * Etot];
__device__ float g_emb[Bb * HIDD];

// ---------------- helpers ----------------
__device__ __forceinline__ uint32_t pack_bf(__nv_bfloat16 a, __nv_bfloat16 b) {
    return ((uint32_t)__bfloat16_as_ushort(b) << 16) | (uint32_t)__bfloat16_as_ushort(a);
}

__device__ __forceinline__ void ldsm4(uint32_t* r, const void* p) {
    uint32_t a = (uint32_t)__cvta_generic_to_shared(p);
    asm volatile("ldmatrix.sync.aligned.m8n8.x4.shared.b16 {%0,%1,%2,%3}, [%4];"
        : "=r"(r[0]), "=r"(r[1]), "=r"(r[2]), "=r"(r[3]) : "r"(a));
}

__device__ __forceinline__ void mma16816(float* d, const uint32_t* a, const uint32_t* b) {
    asm volatile("mma.sync.aligned.m16n8k16.row.col.f32.bf16.bf16.f32 "
        "{%0,%1,%2,%3}, {%4,%5,%6,%7}, {%8,%9}, {%0,%1,%2,%3};"
        : "+f"(d[0]), "+f"(d[1]), "+f"(d[2]), "+f"(d[3])
        : "r"(a[0]), "r"(a[1]), "r"(a[2]), "r"(a[3]), "r"(b[0]), "r"(b[1]));
}

// ---------------- CSR build ----------------
__global__ void k_zerocnt() {
    int i = blockIdx.x * blockDim.x + threadIdx.x;
    if (i < Bb * Nn) g_cnt[i] = 0;
}

__global__ void k_hist(const int* __restrict__ ei) {
    int i = blockIdx.x * blockDim.x + threadIdx.x;
    if (i >= Bb * Etot) return;
    int g = i / Etot, e = i - g * Etot;
    int dst = (e < Eraw) ? ei[(g * 2 + 1) * Eraw + e] : (e - Eraw);
    atomicAdd(&g_cnt[g * Nn + dst], 1);
}

__global__ void k_scan() {
    int g = blockIdx.x;
    __shared__ int sh[1024];
    int t = threadIdx.x;
    const int* cnt = g_cnt + g * Nn;
    int b4 = t * 4;
    int v0 = cnt[b4], v1 = cnt[b4 + 1], v2 = cnt[b4 + 2], v3 = cnt[b4 + 3];
    int s1 = v0, s2 = s1 + v1, s3 = s2 + v2, s4 = s3 + v3;
    sh[t] = s4;
    __syncthreads();
    for (int off = 1; off < 1024; off <<= 1) {
        int x = (t >= off) ? sh[t - off] : 0;
        __syncthreads();
        sh[t] += x;
        __syncthreads();
    }
    int base = sh[t] - s4;
    int* rp  = g_rp  + g * (Nn + 1);
    int* cur = g_cur + g * Nn;
    if (t == 0) rp[0] = 0;
    rp[b4 + 1] = base + s1; rp[b4 + 2] = base + s2;
    rp[b4 + 3] = base + s3; rp[b4 + 4] = base + s4;
    cur[b4] = base; cur[b4 + 1] = base + s1; cur[b4 + 2] = base + s2; cur[b4 + 3] = base + s3;
}

__global__ void k_scatter(const int* __restrict__ ei) {
    int i = blockIdx.x * blockDim.x + threadIdx.x;
    if (i >= Bb * Etot) return;
    int g = i / Etot, e = i - g * Etot;
    int src, dst;
    if (e < Eraw) { src = ei[(g * 2) * Eraw + e]; dst = ei[(g * 2 + 1) * Eraw + e]; }
    else          { src = e - Eraw; dst = src; }
    int pos = atomicAdd(&g_cur[g * Nn + dst], 1);
    g_csrc[g * Etot + pos] = src;
}

// ---------------- conversions (hi/lo bf16 split) ----------------
__global__ void k_cvt_wt(const float* __restrict__ W1, const float* __restrict__ W2,
                         const float* __restrict__ W3) {
    int i = blockIdx.x * blockDim.x + threadIdx.x;
    if (i >= WTALL) return;
    float v;
    if (i < WT1) {
        int n = i / Fin, k = i - n * Fin;
        v = W1[k * HD + n];
    } else if (i < WT1 + WT2) {
        int j = i - WT1; int n = j / HD, k = j - n * HD;
        v = W2[k * HD + n];
    } else {
        int j = i - WT1 - WT2; int n = j / HD, k = j - n * HD;
        v = W3[k * HIDD + n];
    }
    __nv_bfloat16 h = __float2bfloat16(v);
    __nv_bfloat16 l = __float2bfloat16(v - __bfloat162float(h));
    g_wth[i] = h; g_wtl[i] = l;
}

__global__ void k_cvt_x(const float* __restrict__ x) {
    int i = blockIdx.x * blockDim.x + threadIdx.x;   // over float4 units
    if (i >= (Mtot * Fin) / 4) return;
    float4 v = ((const float4*)x)[i];
    __nv_bfloat16 h0 = __float2bfloat16(v.x), h1 = __float2bfloat16(v.y);
    __nv_bfloat16 h2 = __float2bfloat16(v.z), h3 = __float2bfloat16(v.w);
    __nv_bfloat16 l0 = __float2bfloat16(v.x - __bfloat162float(h0));
    __nv_bfloat16 l1 = __float2bfloat16(v.y - __bfloat162float(h1));
    __nv_bfloat16 l2 = __float2bfloat16(v.z - __bfloat162float(h2));
    __nv_bfloat16 l3 = __float2bfloat16(v.w - __bfloat162float(h3));
    uint2 uh; uh.x = pack_bf(h0, h1); uh.y = pack_bf(h2, h3);
    uint2 ul; ul.x = pack_bf(l0, l1); ul.y = pack_bf(l2, l3);
    ((uint2*)g_xh)[i] = uh;
    ((uint2*)g_xl)[i] = ul;
}

// ---------------- mma.sync bf16 GEMM (3-term hi/lo) + fused attention epilogue ---------
// C[M x Nfull] = A[M x K] * Bt[Nfull x K]^T, Nfull = gridDim.x * 64, one head per CTA col.
// CTA: 256 thr = 8 warps (4M x 2N); CTA tile 128x64; warp tile 32x32; K-chunk 32.
__global__ __launch_bounds__(256)
void mma_gemm(const __nv_bfloat16* __restrict__ Ah, const __nv_bfloat16* __restrict__ Al,
              const __nv_bfloat16* __restrict__ Bth, const __nv_bfloat16* __restrict__ Btl,
              float* __restrict__ C, int K,
              const float* __restrict__ atts, const float* __restrict__ attd) {
    __shared__ __align__(16) __nv_bfloat16 sA[2][128][40];  // [hi/lo][m][k] pad->80B rows
    __shared__ __align__(16) __nv_bfloat16 sB[2][64][40];
    __shared__ float sas[128][2], sad[128][2];

    const int tid  = threadIdx.x;
    const int lane = tid & 31;
    const int warp = tid >> 5;
    const int wm = warp >> 1, wn = warp & 1;
    const int row0 = blockIdx.y * 128;
    const int head = blockIdx.x;
    const int H = gridDim.x;
    const int Nfull = H * 64;
    const int n0 = head * 64;

    float d[2][4][4];
#pragma unroll
    for (int mi = 0; mi < 2; mi++)
#pragma unroll
        for (int ni = 0; ni < 4; ni++)
#pragma unroll
            for (int j = 0; j < 4; j++) d[mi][ni][j] = 0.f;

    // fragment smem addresses (constant across chunks except ks term)
    const int a_row = wm * 32 + (lane & 15);
    const int a_colbase = (lane >> 4) * 8;
    const int b_rowbase = wn * 32 + (lane >> 4) * 8 + (lane & 7);
    const int b_colbase = ((lane >> 3) & 1) * 8;

    const int nchunks = K >> 5;
    for (int ch = 0; ch < nchunks; ch++) {
        const int k0 = ch << 5;
        // load A tile: 2 bufs x 128 rows x 32k, 16B units
#pragma unroll
        for (int u = tid; u < 1024; u += 256) {
            int buf = u >> 9, rem = u & 511;
            int r = rem >> 2, c = rem & 3;
            const __nv_bfloat16* src = (buf ? Al : Ah) + (size_t)(row0 + r) * K + k0 + c * 8;
            *(uint4*)&sA[buf][r][c * 8] = *(const uint4*)src;
        }
        // load B tile: 2 bufs x 64 rows x 32k
#pragma unroll
        for (int u = tid; u < 512; u += 256) {
            int buf = u >> 8, rem = u & 255;
            int r = rem >> 2, c = rem & 3;
            const __nv_bfloat16* src = (buf ? Btl : Bth) + (size_t)(n0 + r) * K + k0 + c * 8;
            *(uint4*)&sB[buf][r][c * 8] = *(const uint4*)src;
        }
        __syncthreads();

#pragma unroll
        for (int ks = 0; ks < 2; ks++) {
            uint32_t ah[2][4], al[2][4];
#pragma unroll
            for (int mi = 0; mi < 2; mi++) {
                ldsm4(ah[mi], &sA[0][a_row + mi * 16][ks * 16 + a_colbase]);
                ldsm4(al[mi], &sA[1][a_row + mi * 16][ks * 16 + a_colbase]);
            }
            uint32_t bh[4][2], bl[4][2];
#pragma unroll
            for (int nb2 = 0; nb2 < 2; nb2++) {
                uint32_t t[4];
                ldsm4(t, &sB[0][b_rowbase + nb2 * 16][ks * 16 + b_colbase]);
                bh[nb2 * 2][0] = t[0]; bh[nb2 * 2][1] = t[1];
                bh[nb2 * 2 + 1][0] = t[2]; bh[nb2 * 2 + 1][1] = t[3];
                ldsm4(t, &sB[1][b_rowbase + nb2 * 16][ks * 16 + b_colbase]);
                bl[nb2 * 2][0] = t[0]; bl[nb2 * 2][1] = t[1];
                bl[nb2 * 2 + 1][0] = t[2]; bl[nb2 * 2 + 1][1] = t[3];
            }
#pragma unroll
            for (int mi = 0; mi < 2; mi++)
#pragma unroll
                for (int ni = 0; ni < 4; ni++) {
                    mma16816(d[mi][ni], ah[mi], bh[ni]);
                    mma16816(d[mi][ni], ah[mi], bl[ni]);
                    mma16816(d[mi][ni], al[mi], bh[ni]);
                }
        }
        __syncthreads();
    }

    // ---- epilogue: store C + fused per-row attention dots ----
    const float* asp = atts + head * 64;
    const float* adp = attd + head * 64;
    float ps[4] = {0.f, 0.f, 0.f, 0.f}, pd[4] = {0.f, 0.f, 0.f, 0.f};
#pragma unroll
    for (int mi = 0; mi < 2; mi++) {
        int rA = row0 + wm * 32 + mi * 16 + (lane >> 2);
#pragma unroll
        for (int ni = 0; ni < 4; ni++) {
            float* dd = d[mi][ni];
            int c = wn * 32 + ni * 8 + (lane & 3) * 2;
            float2 v0; v0.x = dd[0]; v0.y = dd[1];
            float2 v1; v1.x = dd[2]; v1.y = dd[3];
            *(float2*)&C[(size_t)rA * Nfull + n0 + c] = v0;
            *(float2*)&C[(size_t)(rA + 8) * Nfull + n0 + c] = v1;
            float s0 = asp[c], s1 = asp[c + 1], d0 = adp[c], d1 = adp[c + 1];
            ps[mi * 2 + 0] += dd[0] * s0 + dd[1] * s1;
            pd[mi * 2 + 0] += dd[0] * d0 + dd[1] * d1;
            ps[mi * 2 + 1] += dd[2] * s0 + dd[3] * s1;
            pd[mi * 2 + 1] += dd[2] * d0 + dd[3] * d1;
        }
    }
#pragma unroll
    for (int j = 0; j < 4; j++) {
        ps[j] += __shfl_xor_sync(0xffffffffu, ps[j], 1);
        ps[j] += __shfl_xor_sync(0xffffffffu, ps[j], 2);
        pd[j] += __shfl_xor_sync(0xffffffffu, pd[j], 1);
        pd[j] += __shfl_xor_sync(0xffffffffu, pd[j], 2);
    }
    if ((lane & 3) == 0) {
#pragma unroll
        for (int mi = 0; mi < 2; mi++) {
            int rloc = wm * 32 + mi * 16 + (lane >> 2);
            sas[rloc][wn] = ps[mi * 2];     sad[rloc][wn] = pd[mi * 2];
            sas[rloc + 8][wn] = ps[mi * 2 + 1]; sad[rloc + 8][wn] = pd[mi * 2 + 1];
        }
    }
    __syncthreads();
    if (tid < 128) {
        g_as[(size_t)(row0 + tid) * H + head] = sas[tid][0] + sas[tid][1];
        g_ad[(size_t)(row0 + tid) * H + head] = sad[tid][0] + sad[tid][1];
    }
}

// ---------------- fused edge-softmax + aggregation: warp per destination ----------------
template <int H, bool DOELU, bool BF16OUT>
__global__ __launch_bounds__(256)
void attn_agg(const float* __restrict__ bias, float* __restrict__ out) {
    constexpr int CH  = H * 64;
    constexpr int PER = CH / 32;
    __shared__ float sh_alpha[8][DEGCAP * H];

    int w = (blockIdx.x * blockDim.x + threadIdx.x) >> 5;
    int wl = (threadIdx.x >> 5);
    int lane = threadIdx.x & 31;
    if (w >= Bb * Nn) return;
    int g = w / Nn, n = w - g * Nn;
    int s = g_rp[g * (Nn + 1) + n], e = g_rp[g * (Nn + 1) + n + 1];

    float adv = 0.f;
    if (lane < H) adv = g_ad[(g * Nn + n) * H + lane];
    float ad_h[H];
#pragma unroll
    for (int h = 0; h < H; h++) ad_h[h] = __shfl_sync(0xffffffffu, adv, h);

    float den[H];
#pragma unroll
    for (int h = 0; h < H; h++) den[h] = 0.f;

    for (int i = s + lane; i < e; i += 32) {
        int src = g_csrc[g * Etot + i];
        float av[H];
        if (H == 4) {
            float4 a4 = *(const float4*)&g_as[((long long)g * Nn + src) * 4];
            av[0] = a4.x; if (H > 1) { av[1] = a4.y; av[2] = a4.z; av[3] = a4.w; }
        } else {
            av[0] = g_as[(g * Nn + src)];
        }
        int rel = i - s;
#pragma unroll
        for (int h = 0; h < H; h++) {
            float eh = av[h] + ad_h[h];
            eh = (eh > 0.f) ? eh : 0.2f * eh;
            float ex = __expf(eh);
            den[h] += ex;
            if (rel < DEGCAP) sh_alpha[wl][rel * H + h] = ex;
        }
    }
#pragma unroll
    for (int h = 0; h < H; h++)
#pragma unroll
        for (int off = 16; off; off >>= 1)
            den[h] += __shfl_xor_sync(0xffffffffu, den[h], off);
    __syncwarp();

    const int head = (lane * PER) >> 6;
    const float invh = 1.f / (den[head] + 1e-16f);
    float adh = ad_h[head];

    float acc[PER];
#pragma unroll
    for (int k = 0; k < PER; k++) acc[k] = 0.f;

    for (int i = s; i < e; i++) {
        int slot = g * Etot + i;
        int src = g_csrc[slot];
        int rel = i - s;
        float ex;
        if (rel < DEGCAP) {
            ex = sh_alpha[wl][rel * H + head];
        } else {
            float a = g_as[((long long)g * Nn + src) * H + head];
            float eh = a + adh;
            eh = (eh > 0.f) ? eh : 0.2f * eh;
            ex = __expf(eh);
        }
        const float* hp = g_h + ((long long)g * Nn + src) * CH + lane * PER;
        if (PER == 8) {
            float4 x0 = __ldg((const float4*)hp);
            float4 x1 = __ldg((const float4*)(hp + 4));
            acc[0] += ex * x0.x; acc[1] += ex * x0.y;
            acc[2] += ex * x0.z; acc[3] += ex * x0.w;
            acc[4] += ex * x1.x; acc[5] += ex * x1.y;
            acc[6] += ex * x1.z; acc[7] += ex * x1.w;
        } else {
            float2 x0 = __ldg((const float2*)hp);
            acc[0] += ex * x0.x; acc[1] += ex * x0.y;
        }
    }

    float v[PER];
#pragma unroll
    for (int k = 0; k < PER; k++) {
        float t = acc[k] * invh + bias[lane * PER + k];
        if (DOELU) t = (t > 0.f) ? t : expm1f(t);
        v[k] = t;
    }
    if (BF16OUT) {
        __nv_bfloat16 hb[PER], lb[PER];
#pragma unroll
        for (int k = 0; k < PER; k++) {
            hb[k] = __float2bfloat16(v[k]);
            lb[k] = __float2bfloat16(v[k] - __bfloat162float(hb[k]));
        }
        size_t base = (size_t)w * CH + lane * PER;
        uint4 uh, ul;
        uh.x = pack_bf(hb[0], hb[1]); uh.y = pack_bf(hb[2], hb[3]);
        uh.z = pack_bf(hb[4], hb[5]); uh.w = pack_bf(hb[6], hb[7]);
        ul.x = pack_bf(lb[0], lb[1]); ul.y = pack_bf(lb[2], lb[3]);
        ul.z = pack_bf(lb[4], lb[5]); ul.w = pack_bf(lb[6], lb[7]);
        *(uint4*)(g_oh + base) = uh;
        *(uint4*)(g_ol + base) = ul;
    } else {
        float* op = out + (size_t)w * CH + lane * PER;
#pragma unroll
        for (int k = 0; k < PER; k++) op[k] = v[k];
    }
}

// ---------------- graph embed: mean over nodes ----------------
__global__ void k_mean() {
    int c = blockIdx.x, g = blockIdx.y;
    __shared__ float sh[256];
    float s = 0.f;
    for (int n = threadIdx.x; n < Nn; n += 256)
        s += g_o[(long long)(g * Nn + n) * HIDD + c];
    sh[threadIdx.x] = s;
    __syncthreads();
    for (int o = 128; o; o >>= 1) {
        if (threadIdx.x < o) sh[threadIdx.x] += sh[threadIdx.x + o];
        __syncthreads();
    }
    if (threadIdx.x == 0) g_emb[g * HIDD + c] = sh[0] * (1.f / Nn);
}

// ---------------- classifier + log-softmax + loss/pred ----------------
__global__ void k_final(const int* __restrict__ labels, const float* __restrict__ Wc,
                        const float* __restrict__ bc, float* __restrict__ out, int out_size) {
    __shared__ float lg[Bb][NCLS];
    __shared__ float nll[Bb];
    __shared__ float predf[Bb];
    int t = threadIdx.x;
    if (t < Bb * NCLS) {
        int g = t / NCLS, c = t - g * NCLS;
        float s = bc[c];
#pragma unroll 8
        for (int d = 0; d < HIDD; d++) s += g_emb[g * HIDD + d] * Wc[d * NCLS + c];
        lg[g][c] = s;
    }
    __syncthreads();
    if (t < Bb) {
        float mx = lg[t][0]; int am = 0;
#pragma unroll
        for (int c = 1; c < NCLS; c++) if (lg[t][c] > mx) { mx = lg[t][c]; am = c; }
        float se = 0.f;
#pragma unroll
        for (int c = 0; c < NCLS; c++) se += expf(lg[t][c] - mx);
        float lse = mx + logf(se);
        nll[t] = lse - lg[t][labels[t]];
        predf[t] = (float)am;
    }
    __syncthreads();
    if (t == 0) {
        float loss = (nll[0] + nll[1] + nll[2] + nll[3]) * 0.25f;
        if (out_size >= 9) {
            for (int g = 0; g < Bb; g++) { out[g] = predf[g]; out[4 + g] = (float)labels[g]; }
            out[8] = loss;
            for (int j = 9; j < out_size; j++) out[j] = 0.f;
        } else if (out_size == 1) {
            out[0] = loss;
        } else if (out_size == 4) {
            for (int g = 0; g < Bb; g++) out[g] = predf[g];
        } else if (out_size == 8) {
            for (int g = 0; g < Bb; g++) { out[g] = predf[g]; out[4 + g] = (float)labels[g]; }
        } else {
            for (int j = 0; j < out_size; j++) out[j] = loss;
        }
    }
}

// ---------------- host launcher ----------------
extern "C" void kernel_launch(void* const* d_in, const int* in_sizes, int n_in,
                              void* d_out, int out_size) {
    const float* x      = (const float*)d_in[0];
    const int*   labels = (const int*)  d_in[1];
    const int*   ei     = (const int*)  d_in[2];
    const float* W1  = (const float*)d_in[3];
    const float* as1 = (const float*)d_in[4];
    const float* ad1 = (const float*)d_in[5];
    const float* b1  = (const float*)d_in[6];
    const float* W2  = (const float*)d_in[7];
    const float* as2 = (const float*)d_in[8];
    const float* ad2 = (const float*)d_in[9];
    const float* b2  = (const float*)d_in[10];
    const float* W3  = (const float*)d_in[11];
    const float* as3 = (const float*)d_in[12];
    const float* ad3 = (const float*)d_in[13];
    const float* b3  = (const float*)d_in[14];
    const float* Wc  = (const float*)d_in[15];
    const float* bc  = (const float*)d_in[16];
    float* out = (float*)d_out;

    float *p_h, *p_o;
    __nv_bfloat16 *p_oh, *p_ol, *p_xh, *p_xl, *p_wth, *p_wtl;
    cudaGetSymbolAddress((void**)&p_h,  g_h);
    cudaGetSymbolAddress((void**)&p_o,  g_o);
    cudaGetSymbolAddress((void**)&p_oh, g_oh);
    cudaGetSymbolAddress((void**)&p_ol, g_ol);
    cudaGetSymbolAddress((void**)&p_xh, g_xh);
    cudaGetSymbolAddress((void**)&p_xl, g_xl);
    cudaGetSymbolAddress((void**)&p_wth, g_wth);
    cudaGetSymbolAddress((void**)&p_wtl, g_wtl);

    const int M = Mtot;
    const int EBLK = (Bb * Etot + 255) / 256;

    // CSR build + conversions
    k_zerocnt<<<(Bb * Nn + 255) / 256, 256>>>();
    k_hist<<<EBLK, 256>>>(ei);
    k_scan<<<Bb, 1024>>>();
    k_scatter<<<EBLK, 256>>>(ei);
    k_cvt_wt<<<(WTALL + 255) / 256, 256>>>(W1, W2, W3);
    k_cvt_x<<<((M * Fin / 4) + 255) / 256, 256>>>(x);

    // layer 1: 768 -> 4x64, concat, elu
    mma_gemm<<<dim3(NHEAD, M / 128), 256>>>(p_xh, p_xl, p_wth, p_wtl, p_h, Fin, as1, ad1);
    attn_agg<NHEAD, true, true><<<M / 8, 256>>>(b1, nullptr);

    // layer 2: 256 -> 4x64, concat, elu
    mma_gemm<<<dim3(NHEAD, M / 128), 256>>>(p_oh, p_ol, p_wth + WT1, p_wtl + WT1, p_h, HD, as2, ad2);
    attn_agg<NHEAD, true, true><<<M / 8, 256>>>(b2, nullptr);

    // layer 3: 256 -> 1x64, no elu, fp32 out
    mma_gemm<<<dim3(1, M / 128), 256>>>(p_oh, p_ol, p_wth + WT1 + WT2, p_wtl + WT1 + WT2, p_h, HD, as3, ad3);
    attn_agg<1, false, false><<<M / 8, 256>>>(b3, p_o);

    // readout + classifier
    k_mean<<<dim3(HIDD, Bb), 256>>>();
    k_final<<<1, 32>>>(labels, Wc, bc, out, out_size);
}